// round 11
// baseline (speedup 1.0000x reference)
#include <cuda_runtime.h>

#define BATCH 64
#define CH 3
#define IMG 640
#define PH 20
#define POOL 32
#define KDIM 1200
#define NQ 300
#define NCCOLS 84
#define NTOT 25200          // NQ * NCCOLS
#define NHALF 12600         // NTOT / 2 (two cols per thread)
#define TOPK 150
#define BT 32               // batch tile per GEMM block (2 b-sweeps)
#define PAIRS (BT / 2)      // 16 f32x2-packed batch pairs per block
#define NPAIRS (BATCH / 2)  // 32 total pairs
#define KCMAX 248           // Eigen threaded kc (FROZEN: matches reference bits)

__device__ float g_pooled[BATCH * KDIM];
__device__ unsigned long long g_pp[KDIM * NPAIRS];   // packed pairs, [k][pair]
__device__ float g_y[BATCH * NTOT];                  // 6.45 MB

typedef unsigned long long ull;

__device__ __forceinline__ ull pack2(float lo, float hi) {
    ull r; asm("mov.b64 %0, {%1, %2};" : "=l"(r) : "f"(lo), "f"(hi)); return r;
}
__device__ __forceinline__ ull dup2(float w) {
    ull r; asm("mov.b64 %0, {%1, %1};" : "=l"(r) : "f"(w)); return r;
}
__device__ __forceinline__ void fma2(ull& acc, ull a, ull b) {
    asm("fma.rn.f32x2 %0, %1, %2, %0;" : "+l"(acc) : "l"(a), "l"(b));
}
__device__ __forceinline__ ull add2(ull a, ull b) {
    ull r; asm("add.rn.f32x2 %0, %1, %2;" : "=l"(r) : "l"(a), "l"(b)); return r;
}
__device__ __forceinline__ void unpack2(ull v, float& lo, float& hi) {
    asm("mov.b64 {%0, %1}, %2;" : "=f"(lo), "=f"(hi) : "l"(v));
}

// ---------------------------------------------------------------------------
// Kernel 1 (FROZEN NUMERICS): 32x32 mean pool + BGR flip.
// pooled = fl( exact_int_sum * fl(1/261120) ); int sum < 2^24 exact.
// One warp per pooled cell. Measured at HBM roofline (82%).
// ---------------------------------------------------------------------------
__global__ void pool_kernel(const int* __restrict__ x) {
    int warp = (blockIdx.x * blockDim.x + threadIdx.x) >> 5;
    int lane = threadIdx.x & 31;
    if (warp >= BATCH * CH * PH * PH) return;
    int pw = warp % PH;
    int ph = (warp / PH) % PH;
    int c  = (warp / (PH * PH)) % CH;
    int b  = warp / (PH * PH * CH);
    int c_in = 2 - c;  // BGR flip
    const int* base = x + (((long)(b * CH + c_in) * IMG + ph * POOL) * IMG) + pw * POOL;
    int rowoff = lane >> 3;        // 0..3
    int coloff = (lane & 7) * 4;   // 0,4,..,28 (ints)
    int sum = 0;
#pragma unroll
    for (int r = 0; r < POOL; r += 4) {
        int4 v = *(const int4*)(base + (r + rowoff) * IMG + coloff);
        sum += v.x + v.y + v.z + v.w;
    }
#pragma unroll
    for (int s = 16; s; s >>= 1) sum += __shfl_xor_sync(0xffffffffu, sum, s);
    if (lane == 0)
        g_pooled[b * KDIM + c * (PH * PH) + ph * PH + pw] =
            (float)sum * (1.0f / 261120.0f);
}

// ---------------------------------------------------------------------------
// Kernel 1b: repack pooled into [k][pair] f32x2 layout so GEMM tile fills
// are contiguous. 307 KB, L2-resident. Bit-neutral (pure data movement).
// ---------------------------------------------------------------------------
__global__ void repack_kernel() {
    int tid = blockIdx.x * blockDim.x + threadIdx.x;
    if (tid >= KDIM * NPAIRS) return;
    int k = tid >> 5;          // KDIM index
    int p = tid & 31;          // pair index
    g_pp[tid] = pack2(g_pooled[(2 * p) * KDIM + k],
                      g_pooled[(2 * p + 1) * KDIM + k]);
}

// ---------------------------------------------------------------------------
// Kernel 2 (FROZEN NUMERICS): one Eigen GEBP K-panel per launch.
// Within the panel: ascending-k fused-FMA chain per (batch, n) from 0.
// Across launches (stream-ordered): g_y = g_y + panel  -> the frozen merge
// ((((p1+p2)+p3)+p4)+p5). 2-column register blocking (n, n+12600), BT=32.
// W prefetched one 4-k group ahead to hide LDG latency.
// ---------------------------------------------------------------------------
__global__ void __launch_bounds__(128) gemm_panel_kernel(
        const float* __restrict__ W, int k0, int len, int first) {
    __shared__ ull p_s[KCMAX][PAIRS];        // 31.7 KB
    int n0 = blockIdx.x * 128 + threadIdx.x; // col 0: [0, 12600)
    int pbase = blockIdx.y * PAIRS;          // this block's 16 pairs
    bool active = (n0 < NHALF);
    int n1 = n0 + NHALF;                     // col 1: [12600, 25200)

    // coalesced tile fill from packed pairs: 128 B contiguous per k row
    for (int idx = threadIdx.x; idx < len * PAIRS; idx += 128) {
        int kk = idx >> 4, pp = idx & 15;
        p_s[kk][pp] = g_pp[(k0 + kk) * NPAIRS + pbase + pp];
    }
    __syncthreads();

    ull acc0[PAIRS], acc1[PAIRS];
#pragma unroll
    for (int i = 0; i < PAIRS; i++) { acc0[i] = 0ull; acc1[i] = 0ull; }

    if (active) {
        const float* wpa = W + (long)k0 * NTOT + n0;
        const float* wpb = W + (long)k0 * NTOT + n1;
        // prefetch group 0
        float a0 = wpa[0], a1 = wpa[NTOT], a2 = wpa[2 * NTOT], a3 = wpa[3 * NTOT];
        float c0 = wpb[0], c1 = wpb[NTOT], c2 = wpb[2 * NTOT], c3 = wpb[3 * NTOT];
        for (int kk = 0; kk < len; kk += 4) {
            // start next group's loads (overlap with current FMAs)
            float na0, na1, na2, na3, nc0, nc1, nc2, nc3;
            if (kk + 4 < len) {
                const float* xa = wpa + 4 * (long)NTOT;
                const float* xb = wpb + 4 * (long)NTOT;
                na0 = xa[0]; na1 = xa[NTOT]; na2 = xa[2 * NTOT]; na3 = xa[3 * NTOT];
                nc0 = xb[0]; nc1 = xb[NTOT]; nc2 = xb[2 * NTOT]; nc3 = xb[3 * NTOT];
            } else {
                na0 = na1 = na2 = na3 = nc0 = nc1 = nc2 = nc3 = 0.0f;
            }
            wpa += 4 * (long)NTOT;
            wpb += 4 * (long)NTOT;
            ull A0 = dup2(a0), A1 = dup2(a1), A2 = dup2(a2), A3 = dup2(a3);
            ull C0 = dup2(c0), C1 = dup2(c1), C2 = dup2(c2), C3 = dup2(c3);
#pragma unroll
            for (int h = 0; h < PAIRS / 2; h++) {
                ulonglong2 q0 = *(const ulonglong2*)&p_s[kk + 0][2 * h];
                ulonglong2 q1 = *(const ulonglong2*)&p_s[kk + 1][2 * h];
                ulonglong2 q2 = *(const ulonglong2*)&p_s[kk + 2][2 * h];
                ulonglong2 q3 = *(const ulonglong2*)&p_s[kk + 3][2 * h];
                // strictly ascending k per accumulator chain (FROZEN)
                fma2(acc0[2 * h], q0.x, A0);
                fma2(acc0[2 * h], q1.x, A1);
                fma2(acc0[2 * h], q2.x, A2);
                fma2(acc0[2 * h], q3.x, A3);
                fma2(acc0[2 * h + 1], q0.y, A0);
                fma2(acc0[2 * h + 1], q1.y, A1);
                fma2(acc0[2 * h + 1], q2.y, A2);
                fma2(acc0[2 * h + 1], q3.y, A3);
                fma2(acc1[2 * h], q0.x, C0);
                fma2(acc1[2 * h], q1.x, C1);
                fma2(acc1[2 * h], q2.x, C2);
                fma2(acc1[2 * h], q3.x, C3);
                fma2(acc1[2 * h + 1], q0.y, C0);
                fma2(acc1[2 * h + 1], q1.y, C1);
                fma2(acc1[2 * h + 1], q2.y, C2);
                fma2(acc1[2 * h + 1], q3.y, C3);
            }
            a0 = na0; a1 = na1; a2 = na2; a3 = na3;
            c0 = nc0; c1 = nc1; c2 = nc2; c3 = nc3;
        }

        // ordered panel merge into g_y (launch order = frozen merge order)
#pragma unroll
        for (int pp = 0; pp < PAIRS; pp++) {
            long rA = (long)(2 * (pbase + pp))     * NTOT;
            long rB = (long)(2 * (pbase + pp) + 1) * NTOT;
            float ya, yb;
            if (first) {
                unpack2(acc0[pp], ya, yb);
                g_y[rA + n0] = ya; g_y[rB + n0] = yb;
                unpack2(acc1[pp], ya, yb);
                g_y[rA + n1] = ya; g_y[rB + n1] = yb;
            } else {
                ull old0 = pack2(g_y[rA + n0], g_y[rB + n0]);
                unpack2(add2(old0, acc0[pp]), ya, yb);
                g_y[rA + n0] = ya; g_y[rB + n0] = yb;
                ull old1 = pack2(g_y[rA + n1], g_y[rB + n1]);
                unpack2(add2(old1, acc1[pp]), ya, yb);
                g_y[rA + n1] = ya; g_y[rB + n1] = yb;
            }
        }
    }
}

// ---------------------------------------------------------------------------
// Kernel 3 (fused score + topk): one block per batch (320 threads).
// Phase 1: warp w handles q = w, w+10, ... — max/argmax over 80 class cols
// (ties -> lower index, matches jnp.argmax). Phase 2: rank-count top-150
// (descending, ties by lower index — matches lax.top_k) and scatter.
// ---------------------------------------------------------------------------
__global__ void __launch_bounds__(320) epilogue_kernel(float* __restrict__ out) {
    __shared__ float s_score[NQ];
    __shared__ int   s_id[NQ];
    int b = blockIdx.x;
    int wid = threadIdx.x >> 5;      // 0..9
    int lane = threadIdx.x & 31;

    for (int q = wid; q < NQ; q += 10) {
        const float* row = g_y + ((long)b * NQ + q) * NCCOLS;
        float best = -3.4e38f;
        int bidx = 0x7fffffff;
        for (int j = lane; j < 80; j += 32) {
            float v = row[4 + j];
            if (v > best) { best = v; bidx = j; }
        }
#pragma unroll
        for (int s = 16; s; s >>= 1) {
            float ov = __shfl_xor_sync(0xffffffffu, best, s);
            int   oi = __shfl_xor_sync(0xffffffffu, bidx, s);
            if (ov > best || (ov == best && oi < bidx)) { best = ov; bidx = oi; }
        }
        if (lane == 0) { s_score[q] = best; s_id[q] = bidx; }
    }
    __syncthreads();

    int q = threadIdx.x;
    if (q < NQ) {
        float v = s_score[q];
        int rank = 0;
        for (int j = 0; j < NQ; j++) {
            float u = s_score[j];
            rank += (u > v) || (u == v && j < q);
        }
        if (rank < TOPK) {
            float* o = out + (long)(b * TOPK + rank) * 6;
            const float* yrow = g_y + ((long)b * NQ + q) * NCCOLS;
            o[0] = yrow[0];
            o[1] = yrow[1];
            o[2] = yrow[2];
            o[3] = yrow[3];
            o[4] = v;
            o[5] = (float)s_id[q];
        }
    }
}

extern "C" void kernel_launch(void* const* d_in, const int* in_sizes, int n_in,
                              void* d_out, int out_size) {
    const int*   x = (const int*)d_in[0];
    const float* W = (const float*)d_in[1];
    float* out = (float*)d_out;

    pool_kernel<<<(BATCH * CH * PH * PH) / 8, 256>>>(x);
    repack_kernel<<<(KDIM * NPAIRS + 255) / 256, 256>>>();

    dim3 gg((NHALF + 127) / 128, BATCH / BT);   // (99, 2)
    // 5 Eigen panels, stream-ordered => frozen merge ((((p1+p2)+p3)+p4)+p5)
    gemm_panel_kernel<<<gg, 128>>>(W, 0,         KCMAX, 1);
    gemm_panel_kernel<<<gg, 128>>>(W, KCMAX,     KCMAX, 0);
    gemm_panel_kernel<<<gg, 128>>>(W, 2 * KCMAX, KCMAX, 0);
    gemm_panel_kernel<<<gg, 128>>>(W, 3 * KCMAX, KCMAX, 0);
    gemm_panel_kernel<<<gg, 128>>>(W, 4 * KCMAX, KDIM - 4 * KCMAX, 0);

    epilogue_kernel<<<BATCH, 320>>>(out);
}

// round 12
// speedup vs baseline: 1.9054x; 1.9054x over previous
#include <cuda_runtime.h>

#define BATCH 64
#define CH 3
#define IMG 640
#define PH 20
#define POOL 32
#define KDIM 1200
#define NQ 300
#define NCCOLS 84
#define NTOT 25200          // NQ * NCCOLS
#define NHALF 12600         // NTOT / 2 (two cols per thread)
#define TOPK 150
#define BT 32               // batch tile per GEMM block (2 b-sweeps)
#define PAIRS (BT / 2)      // 16 f32x2-packed batch pairs per block
#define NPAIRS (BATCH / 2)  // 32 total pairs
#define KCMAX 248           // Eigen threaded kc (FROZEN: matches reference bits)
#define NPANEL 5            // 248,248,248,248,208

__device__ float g_pooled[BATCH * KDIM];
__device__ unsigned long long g_pp[KDIM * NPAIRS];   // packed pairs, [k][pair]
__device__ float g_part[NPANEL][BATCH * NTOT];       // per-panel partials, 32 MB
__device__ float g_y[BATCH * NTOT];                  // 6.45 MB

typedef unsigned long long ull;

__device__ __forceinline__ ull pack2(float lo, float hi) {
    ull r; asm("mov.b64 %0, {%1, %2};" : "=l"(r) : "f"(lo), "f"(hi)); return r;
}
__device__ __forceinline__ ull dup2(float w) {
    ull r; asm("mov.b64 %0, {%1, %1};" : "=l"(r) : "f"(w)); return r;
}
__device__ __forceinline__ void fma2(ull& acc, ull a, ull b) {
    asm("fma.rn.f32x2 %0, %1, %2, %0;" : "+l"(acc) : "l"(a), "l"(b));
}
__device__ __forceinline__ ull add2(ull a, ull b) {
    ull r; asm("add.rn.f32x2 %0, %1, %2;" : "=l"(r) : "l"(a), "l"(b)); return r;
}
__device__ __forceinline__ void unpack2(ull v, float& lo, float& hi) {
    asm("mov.b64 {%0, %1}, %2;" : "=f"(lo), "=f"(hi) : "l"(v));
}

// ---------------------------------------------------------------------------
// Kernel 1 (FROZEN NUMERICS): 32x32 mean pool + BGR flip.
// pooled = fl( exact_int_sum * fl(1/261120) ); int sum < 2^24 exact.
// One warp per pooled cell. At HBM roofline (82%) — compulsory 314 MB.
// ---------------------------------------------------------------------------
__global__ void pool_kernel(const int* __restrict__ x) {
    int warp = (blockIdx.x * blockDim.x + threadIdx.x) >> 5;
    int lane = threadIdx.x & 31;
    if (warp >= BATCH * CH * PH * PH) return;
    int pw = warp % PH;
    int ph = (warp / PH) % PH;
    int c  = (warp / (PH * PH)) % CH;
    int b  = warp / (PH * PH * CH);
    int c_in = 2 - c;  // BGR flip
    const int* base = x + (((long)(b * CH + c_in) * IMG + ph * POOL) * IMG) + pw * POOL;
    int rowoff = lane >> 3;        // 0..3
    int coloff = (lane & 7) * 4;   // 0,4,..,28 (ints)
    int sum = 0;
#pragma unroll
    for (int r = 0; r < POOL; r += 4) {
        int4 v = *(const int4*)(base + (r + rowoff) * IMG + coloff);
        sum += v.x + v.y + v.z + v.w;
    }
#pragma unroll
    for (int s = 16; s; s >>= 1) sum += __shfl_xor_sync(0xffffffffu, sum, s);
    if (lane == 0)
        g_pooled[b * KDIM + c * (PH * PH) + ph * PH + pw] =
            (float)sum * (1.0f / 261120.0f);
}

// ---------------------------------------------------------------------------
// Kernel 1b: repack pooled into [k][pair] f32x2 layout (coalesced GEMM fills).
// ---------------------------------------------------------------------------
__global__ void repack_kernel() {
    int tid = blockIdx.x * blockDim.x + threadIdx.x;
    if (tid >= KDIM * NPAIRS) return;
    int k = tid >> 5;          // KDIM index
    int p = tid & 31;          // pair index
    g_pp[tid] = pack2(g_pooled[(2 * p) * KDIM + k],
                      g_pooled[(2 * p + 1) * KDIM + k]);
}

// ---------------------------------------------------------------------------
// Kernel 2 (FROZEN NUMERICS per chain): all 5 Eigen kc=248 panels run
// CONCURRENTLY (grid.z = panel). Each block: ascending-k fused-FMA chain
// per (batch, n) from 0 over its panel -> g_part[panel]. 2-column register
// blocking (n, n+12600), BT=32. 990 blocks -> ~16 warps/SM (fixes R11's
// 1.34-blocks/SM latency starvation).
// ---------------------------------------------------------------------------
__global__ void __launch_bounds__(128) gemm_panel_kernel(const float* __restrict__ W) {
    __shared__ ull p_s[KCMAX][PAIRS];        // 31.7 KB
    int pan = blockIdx.z;
    int k0  = pan * KCMAX;
    int len = (pan == NPANEL - 1) ? (KDIM - 4 * KCMAX) : KCMAX;   // 208 last
    int n0 = blockIdx.x * 128 + threadIdx.x; // col 0: [0, 12600)
    int pbase = blockIdx.y * PAIRS;          // this block's 16 pairs
    bool active = (n0 < NHALF);
    int n1 = n0 + NHALF;                     // col 1: [12600, 25200)

    // coalesced tile fill: 128 B contiguous per k row
    for (int idx = threadIdx.x; idx < len * PAIRS; idx += 128) {
        int kk = idx >> 4, pp = idx & 15;
        p_s[kk][pp] = g_pp[(k0 + kk) * NPAIRS + pbase + pp];
    }
    __syncthreads();

    ull acc0[PAIRS], acc1[PAIRS];
#pragma unroll
    for (int i = 0; i < PAIRS; i++) { acc0[i] = 0ull; acc1[i] = 0ull; }

    if (active) {
        const float* wpa = W + (long)k0 * NTOT + n0;
        const float* wpb = W + (long)k0 * NTOT + n1;
        for (int kk = 0; kk < len; kk += 4) {
            float a0 = wpa[0];
            float a1 = wpa[NTOT];
            float a2 = wpa[2 * NTOT];
            float a3 = wpa[3 * NTOT];
            float c0 = wpb[0];
            float c1 = wpb[NTOT];
            float c2 = wpb[2 * NTOT];
            float c3 = wpb[3 * NTOT];
            wpa += 4 * (long)NTOT;
            wpb += 4 * (long)NTOT;
            ull A0 = dup2(a0), A1 = dup2(a1), A2 = dup2(a2), A3 = dup2(a3);
            ull C0 = dup2(c0), C1 = dup2(c1), C2 = dup2(c2), C3 = dup2(c3);
#pragma unroll
            for (int h = 0; h < PAIRS / 2; h++) {
                ulonglong2 q0 = *(const ulonglong2*)&p_s[kk + 0][2 * h];
                ulonglong2 q1 = *(const ulonglong2*)&p_s[kk + 1][2 * h];
                ulonglong2 q2 = *(const ulonglong2*)&p_s[kk + 2][2 * h];
                ulonglong2 q3 = *(const ulonglong2*)&p_s[kk + 3][2 * h];
                // strictly ascending k per accumulator chain (FROZEN)
                fma2(acc0[2 * h], q0.x, A0);
                fma2(acc0[2 * h], q1.x, A1);
                fma2(acc0[2 * h], q2.x, A2);
                fma2(acc0[2 * h], q3.x, A3);
                fma2(acc0[2 * h + 1], q0.y, A0);
                fma2(acc0[2 * h + 1], q1.y, A1);
                fma2(acc0[2 * h + 1], q2.y, A2);
                fma2(acc0[2 * h + 1], q3.y, A3);
                fma2(acc1[2 * h], q0.x, C0);
                fma2(acc1[2 * h], q1.x, C1);
                fma2(acc1[2 * h], q2.x, C2);
                fma2(acc1[2 * h], q3.x, C3);
                fma2(acc1[2 * h + 1], q0.y, C0);
                fma2(acc1[2 * h + 1], q1.y, C1);
                fma2(acc1[2 * h + 1], q2.y, C2);
                fma2(acc1[2 * h + 1], q3.y, C3);
            }
        }

        float* part = g_part[pan];
#pragma unroll
        for (int pp = 0; pp < PAIRS; pp++) {
            long rA = (long)(2 * (pbase + pp))     * NTOT;
            long rB = (long)(2 * (pbase + pp) + 1) * NTOT;
            float ya, yb;
            unpack2(acc0[pp], ya, yb);
            part[rA + n0] = ya; part[rB + n0] = yb;
            unpack2(acc1[pp], ya, yb);
            part[rA + n1] = ya; part[rB + n1] = yb;
        }
    }
}

// ---------------------------------------------------------------------------
// Kernel 2b (FROZEN NUMERICS): ordered panel merge,
// y = ((((p0+p1)+p2)+p3)+p4), element-wise IEEE adds (packed f32x2 ==
// scalar rounding). Partials are L2-resident.
// ---------------------------------------------------------------------------
__global__ void merge_kernel() {
    int tid = blockIdx.x * blockDim.x + threadIdx.x;
    if (tid >= BATCH * NTOT / 2) return;
    ull v = ((const ull*)g_part[0])[tid];
    v = add2(v, ((const ull*)g_part[1])[tid]);
    v = add2(v, ((const ull*)g_part[2])[tid]);
    v = add2(v, ((const ull*)g_part[3])[tid]);
    v = add2(v, ((const ull*)g_part[4])[tid]);
    ((ull*)g_y)[tid] = v;
}

// ---------------------------------------------------------------------------
// Kernel 3 (fused score + topk): one block per batch (320 threads).
// Phase 1: max/argmax over 80 class cols (ties -> lower index).
// Phase 2: rank-count top-150 (descending, ties by lower index) + scatter.
// ---------------------------------------------------------------------------
__global__ void __launch_bounds__(320) epilogue_kernel(float* __restrict__ out) {
    __shared__ float s_score[NQ];
    __shared__ int   s_id[NQ];
    int b = blockIdx.x;
    int wid = threadIdx.x >> 5;      // 0..9
    int lane = threadIdx.x & 31;

    for (int q = wid; q < NQ; q += 10) {
        const float* row = g_y + ((long)b * NQ + q) * NCCOLS;
        float best = -3.4e38f;
        int bidx = 0x7fffffff;
        for (int j = lane; j < 80; j += 32) {
            float v = row[4 + j];
            if (v > best) { best = v; bidx = j; }
        }
#pragma unroll
        for (int s = 16; s; s >>= 1) {
            float ov = __shfl_xor_sync(0xffffffffu, best, s);
            int   oi = __shfl_xor_sync(0xffffffffu, bidx, s);
            if (ov > best || (ov == best && oi < bidx)) { best = ov; bidx = oi; }
        }
        if (lane == 0) { s_score[q] = best; s_id[q] = bidx; }
    }
    __syncthreads();

    int q = threadIdx.x;
    if (q < NQ) {
        float v = s_score[q];
        int rank = 0;
        for (int j = 0; j < NQ; j++) {
            float u = s_score[j];
            rank += (u > v) || (u == v && j < q);
        }
        if (rank < TOPK) {
            float* o = out + (long)(b * TOPK + rank) * 6;
            const float* yrow = g_y + ((long)b * NQ + q) * NCCOLS;
            o[0] = yrow[0];
            o[1] = yrow[1];
            o[2] = yrow[2];
            o[3] = yrow[3];
            o[4] = v;
            o[5] = (float)s_id[q];
        }
    }
}

extern "C" void kernel_launch(void* const* d_in, const int* in_sizes, int n_in,
                              void* d_out, int out_size) {
    const int*   x = (const int*)d_in[0];
    const float* W = (const float*)d_in[1];
    float* out = (float*)d_out;

    pool_kernel<<<(BATCH * CH * PH * PH) / 8, 256>>>(x);
    repack_kernel<<<(KDIM * NPAIRS + 255) / 256, 256>>>();

    dim3 gg((NHALF + 127) / 128, BATCH / BT, NPANEL);   // (99, 2, 5) = 990 blocks
    gemm_panel_kernel<<<gg, 128>>>(W);

    merge_kernel<<<(BATCH * NTOT / 2 + 255) / 256, 256>>>();

    epilogue_kernel<<<BATCH, 320>>>(out);
}